// round 8
// baseline (speedup 1.0000x reference)
#include <cuda_runtime.h>
#include <cuda_fp16.h>
#include <math.h>
#include <stdint.h>

#define TT 2048
#define HH 2048
#define II 1024
#define EE 32
#define TOPK 4
#define NROUTED (TT*TOPK)
#define NPAIRS  (NROUTED + TT)

// GEMM tiling
#define BM 256
#define BN 128
#define BK 32
#define NTHR 512
#define ROWB 80                    // 32 fp16 = 64B + 16B pad
#define OFF_A 0
#define OFF_B 20480                // 256*80
#define BUFSZ 30720                // + 128*80
#define SMEM_DYN (2*BUFSZ)

// fp16 weight cache layout (element offsets)
#define OW1  0ULL
#define OW3  67108864ULL
#define OW2  134217728ULL
#define OWS1 201326592ULL
#define OWS3 203423744ULL
#define OWS2 205520896ULL
#define WTOT 207618048ULL

// ---------------- device scratch ----------------
__device__ int   g_counts[EE];
__device__ int   g_cursor[EE];
__device__ int   g_offsets[EE];
__device__ int   g_topk_idx[NROUTED];
__device__ float g_topk_w[NROUTED];
__device__ int   g_pair_token[NROUTED];
__device__ int   g_pair_pos[NROUTED];
__device__ __half g_wh[WTOT];
__device__ __half g_xh[(size_t)TT*HH];
__device__ float g_C1[(size_t)NPAIRS*II];
__device__ float g_C3[(size_t)NPAIRS*II];
__device__ __half g_acth[(size_t)NPAIRS*II];
__device__ float g_pairout[(size_t)NPAIRS*HH];

// ---------------- helpers ----------------
__device__ __forceinline__ void cvt2h(unsigned &r, float hi_elem, float lo_elem) {
    asm("cvt.rn.f16x2.f32 %0, %1, %2;" : "=r"(r) : "f"(hi_elem), "f"(lo_elem));
}
__device__ __forceinline__ void ldsm4(unsigned &r0, unsigned &r1, unsigned &r2, unsigned &r3,
                                      unsigned addr) {
    asm volatile("ldmatrix.sync.aligned.m8n8.x4.shared.b16 {%0,%1,%2,%3}, [%4];"
                 : "=r"(r0), "=r"(r1), "=r"(r2), "=r"(r3) : "r"(addr));
}
__device__ __forceinline__ void mma16816(float* c, const unsigned* a, unsigned b0, unsigned b1) {
    asm volatile("mma.sync.aligned.m16n8k16.row.col.f32.f16.f16.f32 "
                 "{%0,%1,%2,%3}, {%4,%5,%6,%7}, {%8,%9}, {%0,%1,%2,%3};"
                 : "+f"(c[0]), "+f"(c[1]), "+f"(c[2]), "+f"(c[3])
                 : "r"(a[0]), "r"(a[1]), "r"(a[2]), "r"(a[3]), "r"(b0), "r"(b1));
}
__device__ __forceinline__ void cp16(unsigned dst, const void* src) {
    asm volatile("cp.async.cg.shared.global [%0], [%1], 16;" :: "r"(dst), "l"(src));
}

// ---------------- weight conversion (runs first; also zeroes counters) ----------------
__global__ __launch_bounds__(256) void convw_kernel(
        const float* __restrict__ w1, const float* __restrict__ w3,
        const float* __restrict__ w2, const float* __restrict__ ws1,
        const float* __restrict__ ws3, const float* __restrict__ ws2)
{
    if (blockIdx.x == 0 && threadIdx.x < EE) {
        g_counts[threadIdx.x] = 0; g_cursor[threadIdx.x] = 0;
    }
    size_t base = (size_t)blockIdx.x * 2048 + (size_t)threadIdx.x * 8;
    const float* src; size_t off;
    if      (base < OW3)  { src = w1;  off = base - OW1;  }
    else if (base < OW2)  { src = w3;  off = base - OW3;  }
    else if (base < OWS1) { src = w2;  off = base - OW2;  }
    else if (base < OWS3) { src = ws1; off = base - OWS1; }
    else if (base < OWS2) { src = ws3; off = base - OWS3; }
    else                  { src = ws2; off = base - OWS2; }
    float4 a = *(const float4*)(src + off);
    float4 b = *(const float4*)(src + off + 4);
    unsigned h01, h23, h45, h67;
    cvt2h(h01, a.y, a.x); cvt2h(h23, a.w, a.z);
    cvt2h(h45, b.y, b.x); cvt2h(h67, b.w, b.z);
    *(uint4*)(g_wh + base) = make_uint4(h01, h23, h45, h67);
}

// ---------------- small kernels ----------------
__global__ void offsets_kernel() {
    if (threadIdx.x == 0) {
        int s = 0;
        for (int e = 0; e < EE; ++e) { g_offsets[e] = s; s += g_counts[e]; }
    }
}
__global__ void scatter_kernel() {
    int t = blockIdx.x * blockDim.x + threadIdx.x;
    if (t >= TT) return;
    #pragma unroll
    for (int j = 0; j < TOPK; ++j) {
        int e = g_topk_idx[t*TOPK + j];
        int pos = g_offsets[e] + atomicAdd(&g_cursor[e], 1);
        g_pair_token[pos] = t;
        g_pair_pos[t*TOPK + j] = pos;
    }
}
__global__ __launch_bounds__(256) void convx_kernel(const float* __restrict__ x) {
    int i = blockIdx.x * 256 + threadIdx.x;
    g_xh[i] = __float2half_rn(x[i]);
}
__global__ __launch_bounds__(256) void act_kernel() {
    size_t i4 = (size_t)blockIdx.x * 256 + threadIdx.x;
    float4 a = ((const float4*)g_C1)[i4];
    float4 b = ((const float4*)g_C3)[i4];
    float v0 = a.x / (1.f + expf(-a.x)) * b.x;
    float v1 = a.y / (1.f + expf(-a.y)) * b.y;
    float v2 = a.z / (1.f + expf(-a.z)) * b.z;
    float v3 = a.w / (1.f + expf(-a.w)) * b.w;
    unsigned h01, h23;
    cvt2h(h01, v1, v0);
    cvt2h(h23, v3, v2);
    ((uint2*)g_acth)[i4] = make_uint2(h01, h23);
}

// ---------------- gate + routing (proven) ----------------
__global__ __launch_bounds__(256) void gate_kernel(
        const float* __restrict__ x, const float* __restrict__ gw,
        const float* __restrict__ bias)
{
    __shared__ float xs[4][HH];
    __shared__ float logits_s[4][EE];
    __shared__ float bias_s[EE];
    int tid = threadIdx.x;
    int t0  = blockIdx.x * 4;
    const float4* xg  = (const float4*)(x + (size_t)t0 * HH);
    float4*       xs4 = (float4*)&xs[0][0];
    #pragma unroll
    for (int i = 0; i < 8; ++i) xs4[tid + i*256] = xg[tid + i*256];
    if (tid < EE) bias_s[tid] = bias[tid];
    __syncthreads();
    int warp = tid >> 5, lane = tid & 31;
    #pragma unroll
    for (int ei = 0; ei < 4; ++ei) {
        int e = warp*4 + ei;
        const float* gr = gw + (size_t)e * HH;
        float a0=0.f, a1=0.f, a2=0.f, a3=0.f;
        for (int h = lane; h < HH; h += 32) {
            float g = gr[h];
            a0 = fmaf(g, xs[0][h], a0); a1 = fmaf(g, xs[1][h], a1);
            a2 = fmaf(g, xs[2][h], a2); a3 = fmaf(g, xs[3][h], a3);
        }
        #pragma unroll
        for (int off = 16; off; off >>= 1) {
            a0 += __shfl_xor_sync(0xffffffffu, a0, off);
            a1 += __shfl_xor_sync(0xffffffffu, a1, off);
            a2 += __shfl_xor_sync(0xffffffffu, a2, off);
            a3 += __shfl_xor_sync(0xffffffffu, a3, off);
        }
        if (lane == 0) {
            logits_s[0][e] = a0; logits_s[1][e] = a1;
            logits_s[2][e] = a2; logits_s[3][e] = a3;
        }
    }
    __syncthreads();
    if (warp < 4) {
        int t = t0 + warp;
        float logit = logits_s[warp][lane];
        float s   = 1.f / (1.f + expf(-logit));
        float sfc = s + bias_s[lane];
        float m1 = sfc, m2 = -INFINITY;
        #pragma unroll
        for (int off = 4; off >= 1; off >>= 1) {
            float o1 = __shfl_xor_sync(0xffffffffu, m1, off);
            float o2 = __shfl_xor_sync(0xffffffffu, m2, off);
            float hi = fmaxf(m1, o1);
            float lo = fmaxf(fminf(m1, o1), fmaxf(m2, o2));
            m1 = hi; m2 = lo;
        }
        float gs = m1 + m2;
        float gv[4];
        gv[0] = __shfl_sync(0xffffffffu, gs, 0);
        gv[1] = __shfl_sync(0xffffffffu, gs, 8);
        gv[2] = __shfl_sync(0xffffffffu, gs, 16);
        gv[3] = __shfl_sync(0xffffffffu, gs, 24);
        int b1 = 0; float v1 = gv[0];
        #pragma unroll
        for (int gg = 1; gg < 4; ++gg) if (gv[gg] > v1) { v1 = gv[gg]; b1 = gg; }
        int b2 = -1; float v2 = -INFINITY;
        #pragma unroll
        for (int gg = 0; gg < 4; ++gg) {
            if (gg == b1) continue;
            if (gv[gg] > v2) { v2 = gv[gg]; b2 = gg; }
        }
        int mygrp = lane >> 3;
        float val = (mygrp == b1 || mygrp == b2) ? sfc : 0.0f;
        int sel_i[TOPK]; float sel_w[TOPK];
        float cur = val;
        #pragma unroll
        for (int j = 0; j < TOPK; ++j) {
            float bv = cur; int bi = lane;
            #pragma unroll
            for (int off = 16; off >= 1; off >>= 1) {
                float ov = __shfl_xor_sync(0xffffffffu, bv, off);
                int   oi = __shfl_xor_sync(0xffffffffu, bi, off);
                if (ov > bv || (ov == bv && oi < bi)) { bv = ov; bi = oi; }
            }
            sel_i[j] = bi;
            sel_w[j] = __shfl_sync(0xffffffffu, s, bi);
            if (lane == bi) cur = -INFINITY;
        }
        if (lane == 0) {
            float sum = sel_w[0] + sel_w[1] + sel_w[2] + sel_w[3];
            float scale = 2.5f / (sum + 1e-20f);
            #pragma unroll
            for (int j = 0; j < TOPK; ++j) {
                g_topk_idx[t*TOPK + j] = sel_i[j];
                g_topk_w[t*TOPK + j]   = sel_w[j] * scale;
                atomicAdd(&g_counts[sel_i[j]], 1);
            }
        }
    }
}

// ---------------- grouped fp16 GEMM, BM=256, all-cp.async loaders ----------------
__global__ void __launch_bounds__(NTHR, 2) gemm_kernel(
    const __half* __restrict__ A, int lda,
    const __half* __restrict__ Wra, const __half* __restrict__ Wsa,
    const __half* __restrict__ Wrb, const __half* __restrict__ Wsb,
    int Kdim, int ybnd, float* __restrict__ Ca, float* __restrict__ Cb,
    int ldc, int gather)
{
    const int g     = blockIdx.z;
    const int mtile = blockIdx.x;
    const int y     = blockIdx.y;

    int m_count, base_pos;
    if (g < EE) { m_count = g_counts[g]; base_pos = g_offsets[g]; }
    else        { m_count = TT;          base_pos = NROUTED; }
    if (mtile * BM >= m_count) return;
    const int rows = min(BM, m_count - mtile * BM);

    const size_t wsz = (size_t)II * HH;
    const __half* W;
    float* C;
    int n0;
    if (y < ybnd) {
        W = (g < EE) ? (Wra + (size_t)g * wsz) : Wsa;
        C = Ca; n0 = y * BN;
    } else {
        W = (g < EE) ? (Wrb + (size_t)g * wsz) : Wsb;
        C = Cb; n0 = (y - ybnd) * BN;
    }

    extern __shared__ char sm[];
    __shared__ int s_toks[BM];
    const unsigned smb = (unsigned)__cvta_generic_to_shared(sm);

    const int tid = threadIdx.x;
    if (tid < BM) {
        int r = min(tid, rows - 1);
        int pos = base_pos + mtile*BM + r;
        s_toks[tid] = gather ? ((g < EE) ? g_pair_token[pos] : (mtile*BM + r)) : pos;
    }
    __syncthreads();

    const int S = Kdim / BK;
    const int warp = tid >> 5, lane = tid & 31;
    const int wm = (warp & 3) * 64;
    const int wn = (warp >> 2) * 32;
    const int l15 = lane & 15, lh = lane >> 4;

    float acc[4][4][4];
    #pragma unroll
    for (int i = 0; i < 4; ++i)
        #pragma unroll
        for (int j = 0; j < 4; ++j)
            #pragma unroll
            for (int q = 0; q < 4; ++q) acc[i][j][q] = 0.f;

    // ---- stage loader (pure cp.async) ----
    // A: 256 rows x 4 chunks(16B) = 1024 ; B: 128 rows x 4 chunks = 512
    #define LOAD_STAGE(dstb, k0) do {                                        \
        _Pragma("unroll")                                                    \
        for (int t = 0; t < 2; ++t) {                                        \
            int c = tid + t*NTHR;                                            \
            int row = c >> 2, ch = c & 3;                                    \
            const __half* srcp = A + (size_t)s_toks[row]*lda + (k0) + ch*8;  \
            cp16((dstb) + OFF_A + row*ROWB + ch*16, srcp);                   \
        }                                                                    \
        {                                                                    \
            int row = tid >> 2, ch = tid & 3;                                \
            const __half* srcp = W + (size_t)(n0+row)*Kdim + (k0) + ch*8;    \
            cp16((dstb) + OFF_B + row*ROWB + ch*16, srcp);                   \
        }                                                                    \
        asm volatile("cp.async.commit_group;");                              \
    } while(0)

    LOAD_STAGE(smb, 0);
    asm volatile("cp.async.wait_group 0;" ::: "memory");
    __syncthreads();

    int buf = 0;
    for (int s = 0; s < S; ++s) {
        const unsigned cb = smb + buf * BUFSZ;
        const unsigned nb = smb + (buf ^ 1) * BUFSZ;
        if (s + 1 < S) LOAD_STAGE(nb, (s + 1) * BK);

        #pragma unroll
        for (int kk = 0; kk < BK; kk += 16) {
            unsigned bh[2][4];
            #pragma unroll
            for (int nf2 = 0; nf2 < 2; ++nf2) {
                unsigned addr = cb + OFF_B + (wn + nf2*16 + l15)*ROWB + (kk + lh*8)*2;
                ldsm4(bh[nf2][0], bh[nf2][1], bh[nf2][2], bh[nf2][3], addr);
            }
            #pragma unroll
            for (int mf = 0; mf < 4; ++mf) {
                unsigned ah[4];
                unsigned addr = cb + OFF_A + (wm + mf*16 + l15)*ROWB + (kk + lh*8)*2;
                ldsm4(ah[0], ah[1], ah[2], ah[3], addr);
                #pragma unroll
                for (int nf2 = 0; nf2 < 2; ++nf2) {
                    #pragma unroll
                    for (int u = 0; u < 2; ++u) {
                        mma16816(acc[mf][nf2*2 + u], ah, bh[nf2][u], bh[nf2][2 + u]);
                    }
                }
            }
        }

        if (s + 1 < S)
            asm volatile("cp.async.wait_group 0;" ::: "memory");
        __syncthreads();
        buf ^= 1;
    }

    // ---- epilogue ----
    const int gq = lane >> 2, tau = lane & 3;
    #pragma unroll
    for (int mf = 0; mf < 4; ++mf) {
        #pragma unroll
        for (int nf = 0; nf < 4; ++nf) {
            int col = n0 + wn + nf*8 + tau*2;
            int r0 = wm + mf*16 + gq;
            int r1 = r0 + 8;
            if (r0 < rows) {
                float* d = C + (size_t)(base_pos + mtile*BM + r0) * ldc + col;
                d[0] = acc[mf][nf][0]; d[1] = acc[mf][nf][1];
            }
            if (r1 < rows) {
                float* d = C + (size_t)(base_pos + mtile*BM + r1) * ldc + col;
                d[0] = acc[mf][nf][2]; d[1] = acc[mf][nf][3];
            }
        }
    }
}

// ---------------- combine ----------------
__global__ __launch_bounds__(256) void combine_kernel(float* __restrict__ out)
{
    const int t = blockIdx.x;
    const int tid = threadIdx.x;
    __shared__ float w[TOPK];
    __shared__ int   pos[TOPK];
    if (tid < TOPK) {
        w[tid]   = g_topk_w[t*TOPK + tid];
        pos[tid] = g_pair_pos[t*TOPK + tid];
    }
    __syncthreads();
    const float4* sh = (const float4*)(g_pairout + (size_t)(NROUTED + t) * HH);
    const float4* p0 = (const float4*)(g_pairout + (size_t)pos[0] * HH);
    const float4* p1 = (const float4*)(g_pairout + (size_t)pos[1] * HH);
    const float4* p2 = (const float4*)(g_pairout + (size_t)pos[2] * HH);
    const float4* p3 = (const float4*)(g_pairout + (size_t)pos[3] * HH);
    float4* o = (float4*)(out + (size_t)t * HH);
    const float w0=w[0], w1=w[1], w2=w[2], w3=w[3];
    #pragma unroll
    for (int it = 0; it < HH/4/256; ++it) {
        int i = tid + it*256;
        float4 acc = sh[i];
        float4 v0 = p0[i], v1 = p1[i], v2 = p2[i], v3 = p3[i];
        acc.x += w0*v0.x + w1*v1.x + w2*v2.x + w3*v3.x;
        acc.y += w0*v0.y + w1*v1.y + w2*v2.y + w3*v3.y;
        acc.z += w0*v0.z + w1*v1.z + w2*v2.z + w3*v3.z;
        acc.w += w0*v0.w + w1*v1.w + w2*v2.w + w3*v3.w;
        o[i] = acc;
    }
}

// ---------------- launch ----------------
extern "C" void kernel_launch(void* const* d_in, const int* in_sizes, int n_in,
                              void* d_out, int out_size)
{
    const float* x    = (const float*)d_in[0];
    const float* gw   = (const float*)d_in[1];
    const float* bias = (const float*)d_in[2];
    const float* w1   = (const float*)d_in[3];
    const float* w3   = (const float*)d_in[4];
    const float* w2   = (const float*)d_in[5];
    const float* ws1  = (const float*)d_in[6];
    const float* ws3  = (const float*)d_in[7];
    const float* ws2  = (const float*)d_in[8];
    float* out = (float*)d_out;

    cudaFuncSetAttribute(gemm_kernel, cudaFuncAttributeMaxDynamicSharedMemorySize, SMEM_DYN);

    convw_kernel<<<(int)(WTOT/2048), 256>>>(w1, w3, w2, ws1, ws3, ws2);
    gate_kernel<<<TT/4, 256>>>(x, gw, bias);
    offsets_kernel<<<1, 32>>>();
    scatter_kernel<<<TT/256, 256>>>();
    convx_kernel<<<TT*HH/256, 256>>>(x);

    __half *wh, *xh, *ah;
    cudaGetSymbolAddress((void**)&wh, g_wh);
    cudaGetSymbolAddress((void**)&xh, g_xh);
    cudaGetSymbolAddress((void**)&ah, g_acth);
    float *c1, *c3, *po;
    cudaGetSymbolAddress((void**)&c1, g_C1);
    cudaGetSymbolAddress((void**)&c3, g_C3);
    cudaGetSymbolAddress((void**)&po, g_pairout);

    // phase A: C1 = X@W1^T (y<8), C3 = X@W3^T (y>=8); K=HH
    gemm_kernel<<<dim3(8, 16, EE+1), NTHR, SMEM_DYN>>>(
        xh, HH, wh + OW1, wh + OWS1, wh + OW3, wh + OWS3, HH, 8, c1, c3, II, 1);
    act_kernel<<<(int)((size_t)NPAIRS*II/4/256), 256>>>();
    // phase B: pairout = act@W2^T; K=II
    gemm_kernel<<<dim3(8, 16, EE+1), NTHR, SMEM_DYN>>>(
        ah, II, wh + OW2, wh + OWS2, wh + OW2, wh + OWS2, II, 16, po, po, HH, 0);
    combine_kernel<<<TT, 256>>>(out);
}

// round 9
// speedup vs baseline: 1.7825x; 1.7825x over previous
#include <cuda_runtime.h>
#include <cuda_fp16.h>
#include <math.h>
#include <stdint.h>

#define TT 2048
#define HH 2048
#define II 1024
#define EE 32
#define TOPK 4
#define NROUTED (TT*TOPK)
#define NPAIRS  (NROUTED + TT)

// GEMM tiling
#define BM 256
#define BN 128
#define BK 32
#define NTHR 512
#define ROWB 80                    // 32 fp16 = 64B + 16B pad
#define OFF_A 0
#define OFF_B 20480                // 256*80
#define BUFSZ 30720                // + 128*80
#define SMEM_DYN (2*BUFSZ)

// fp16 weight cache layout (element offsets)
#define OW1  0ULL
#define OW3  67108864ULL
#define OW2  134217728ULL
#define OWS1 201326592ULL
#define OWS3 203423744ULL
#define OWS2 205520896ULL
#define WTOT 207618048ULL

// ---------------- device scratch ----------------
__device__ int   g_counts[EE];
__device__ int   g_cursor[EE];
__device__ int   g_offsets[EE];
__device__ int   g_topk_idx[NROUTED];
__device__ float g_topk_w[NROUTED];
__device__ int   g_pair_token[NROUTED];
__device__ int   g_pair_pos[NROUTED];
__device__ __half g_wh[WTOT];
__device__ __half g_xh[(size_t)TT*HH];
__device__ float g_C1[(size_t)NPAIRS*II];
__device__ float g_C3[(size_t)NPAIRS*II];
__device__ __half g_acth[(size_t)NPAIRS*II];
__device__ float g_pairout[(size_t)NPAIRS*HH];

// ---------------- helpers ----------------
__device__ __forceinline__ void cvt2h(unsigned &r, float hi_elem, float lo_elem) {
    asm("cvt.rn.f16x2.f32 %0, %1, %2;" : "=r"(r) : "f"(hi_elem), "f"(lo_elem));
}
__device__ __forceinline__ void ldsm4(unsigned &r0, unsigned &r1, unsigned &r2, unsigned &r3,
                                      unsigned addr) {
    asm volatile("ldmatrix.sync.aligned.m8n8.x4.shared.b16 {%0,%1,%2,%3}, [%4];"
                 : "=r"(r0), "=r"(r1), "=r"(r2), "=r"(r3) : "r"(addr));
}
__device__ __forceinline__ void mma16816(float* c, const unsigned* a, unsigned b0, unsigned b1) {
    asm volatile("mma.sync.aligned.m16n8k16.row.col.f32.f16.f16.f32 "
                 "{%0,%1,%2,%3}, {%4,%5,%6,%7}, {%8,%9}, {%0,%1,%2,%3};"
                 : "+f"(c[0]), "+f"(c[1]), "+f"(c[2]), "+f"(c[3])
                 : "r"(a[0]), "r"(a[1]), "r"(a[2]), "r"(a[3]), "r"(b0), "r"(b1));
}
__device__ __forceinline__ void cp16(unsigned dst, const void* src) {
    asm volatile("cp.async.cg.shared.global [%0], [%1], 16;" :: "r"(dst), "l"(src));
}

// ---------------- weight conversion (runs first; also zeroes counters) ----------------
__global__ __launch_bounds__(256) void convw_kernel(
        const float* __restrict__ w1, const float* __restrict__ w3,
        const float* __restrict__ w2, const float* __restrict__ ws1,
        const float* __restrict__ ws3, const float* __restrict__ ws2)
{
    if (blockIdx.x == 0 && threadIdx.x < EE) {
        g_counts[threadIdx.x] = 0; g_cursor[threadIdx.x] = 0;
    }
    size_t base = (size_t)blockIdx.x * 2048 + (size_t)threadIdx.x * 8;
    const float* src; size_t off;
    if      (base < OW3)  { src = w1;  off = base - OW1;  }
    else if (base < OW2)  { src = w3;  off = base - OW3;  }
    else if (base < OWS1) { src = w2;  off = base - OW2;  }
    else if (base < OWS3) { src = ws1; off = base - OWS1; }
    else if (base < OWS2) { src = ws3; off = base - OWS3; }
    else                  { src = ws2; off = base - OWS2; }
    float4 a = *(const float4*)(src + off);
    float4 b = *(const float4*)(src + off + 4);
    unsigned h01, h23, h45, h67;
    cvt2h(h01, a.y, a.x); cvt2h(h23, a.w, a.z);
    cvt2h(h45, b.y, b.x); cvt2h(h67, b.w, b.z);
    *(uint4*)(g_wh + base) = make_uint4(h01, h23, h45, h67);
}

// ---------------- small kernels ----------------
__global__ void offsets_kernel() {
    if (threadIdx.x == 0) {
        int s = 0;
        for (int e = 0; e < EE; ++e) { g_offsets[e] = s; s += g_counts[e]; }
    }
}
__global__ void scatter_kernel() {
    int t = blockIdx.x * blockDim.x + threadIdx.x;
    if (t >= TT) return;
    #pragma unroll
    for (int j = 0; j < TOPK; ++j) {
        int e = g_topk_idx[t*TOPK + j];
        int pos = g_offsets[e] + atomicAdd(&g_cursor[e], 1);
        g_pair_token[pos] = t;
        g_pair_pos[t*TOPK + j] = pos;
    }
}
__global__ __launch_bounds__(256) void convx_kernel(const float* __restrict__ x) {
    int i = blockIdx.x * 256 + threadIdx.x;
    g_xh[i] = __float2half_rn(x[i]);
}
__global__ __launch_bounds__(256) void act_kernel() {
    size_t i4 = (size_t)blockIdx.x * 256 + threadIdx.x;
    float4 a = ((const float4*)g_C1)[i4];
    float4 b = ((const float4*)g_C3)[i4];
    float v0 = a.x / (1.f + expf(-a.x)) * b.x;
    float v1 = a.y / (1.f + expf(-a.y)) * b.y;
    float v2 = a.z / (1.f + expf(-a.z)) * b.z;
    float v3 = a.w / (1.f + expf(-a.w)) * b.w;
    unsigned h01, h23;
    cvt2h(h01, v1, v0);
    cvt2h(h23, v3, v2);
    ((uint2*)g_acth)[i4] = make_uint2(h01, h23);
}

// ---------------- gate + routing (proven) ----------------
__global__ __launch_bounds__(256) void gate_kernel(
        const float* __restrict__ x, const float* __restrict__ gw,
        const float* __restrict__ bias)
{
    __shared__ float xs[4][HH];
    __shared__ float logits_s[4][EE];
    __shared__ float bias_s[EE];
    int tid = threadIdx.x;
    int t0  = blockIdx.x * 4;
    const float4* xg  = (const float4*)(x + (size_t)t0 * HH);
    float4*       xs4 = (float4*)&xs[0][0];
    #pragma unroll
    for (int i = 0; i < 8; ++i) xs4[tid + i*256] = xg[tid + i*256];
    if (tid < EE) bias_s[tid] = bias[tid];
    __syncthreads();
    int warp = tid >> 5, lane = tid & 31;
    #pragma unroll
    for (int ei = 0; ei < 4; ++ei) {
        int e = warp*4 + ei;
        const float* gr = gw + (size_t)e * HH;
        float a0=0.f, a1=0.f, a2=0.f, a3=0.f;
        for (int h = lane; h < HH; h += 32) {
            float g = gr[h];
            a0 = fmaf(g, xs[0][h], a0); a1 = fmaf(g, xs[1][h], a1);
            a2 = fmaf(g, xs[2][h], a2); a3 = fmaf(g, xs[3][h], a3);
        }
        #pragma unroll
        for (int off = 16; off; off >>= 1) {
            a0 += __shfl_xor_sync(0xffffffffu, a0, off);
            a1 += __shfl_xor_sync(0xffffffffu, a1, off);
            a2 += __shfl_xor_sync(0xffffffffu, a2, off);
            a3 += __shfl_xor_sync(0xffffffffu, a3, off);
        }
        if (lane == 0) {
            logits_s[0][e] = a0; logits_s[1][e] = a1;
            logits_s[2][e] = a2; logits_s[3][e] = a3;
        }
    }
    __syncthreads();
    if (warp < 4) {
        int t = t0 + warp;
        float logit = logits_s[warp][lane];
        float s   = 1.f / (1.f + expf(-logit));
        float sfc = s + bias_s[lane];
        float m1 = sfc, m2 = -INFINITY;
        #pragma unroll
        for (int off = 4; off >= 1; off >>= 1) {
            float o1 = __shfl_xor_sync(0xffffffffu, m1, off);
            float o2 = __shfl_xor_sync(0xffffffffu, m2, off);
            float hi = fmaxf(m1, o1);
            float lo = fmaxf(fminf(m1, o1), fmaxf(m2, o2));
            m1 = hi; m2 = lo;
        }
        float gs = m1 + m2;
        float gv[4];
        gv[0] = __shfl_sync(0xffffffffu, gs, 0);
        gv[1] = __shfl_sync(0xffffffffu, gs, 8);
        gv[2] = __shfl_sync(0xffffffffu, gs, 16);
        gv[3] = __shfl_sync(0xffffffffu, gs, 24);
        int b1 = 0; float v1 = gv[0];
        #pragma unroll
        for (int gg = 1; gg < 4; ++gg) if (gv[gg] > v1) { v1 = gv[gg]; b1 = gg; }
        int b2 = -1; float v2 = -INFINITY;
        #pragma unroll
        for (int gg = 0; gg < 4; ++gg) {
            if (gg == b1) continue;
            if (gv[gg] > v2) { v2 = gv[gg]; b2 = gg; }
        }
        int mygrp = lane >> 3;
        float val = (mygrp == b1 || mygrp == b2) ? sfc : 0.0f;
        int sel_i[TOPK]; float sel_w[TOPK];
        float cur = val;
        #pragma unroll
        for (int j = 0; j < TOPK; ++j) {
            float bv = cur; int bi = lane;
            #pragma unroll
            for (int off = 16; off >= 1; off >>= 1) {
                float ov = __shfl_xor_sync(0xffffffffu, bv, off);
                int   oi = __shfl_xor_sync(0xffffffffu, bi, off);
                if (ov > bv || (ov == bv && oi < bi)) { bv = ov; bi = oi; }
            }
            sel_i[j] = bi;
            sel_w[j] = __shfl_sync(0xffffffffu, s, bi);
            if (lane == bi) cur = -INFINITY;
        }
        if (lane == 0) {
            float sum = sel_w[0] + sel_w[1] + sel_w[2] + sel_w[3];
            float scale = 2.5f / (sum + 1e-20f);
            #pragma unroll
            for (int j = 0; j < TOPK; ++j) {
                g_topk_idx[t*TOPK + j] = sel_i[j];
                g_topk_w[t*TOPK + j]   = sel_w[j] * scale;
                atomicAdd(&g_counts[sel_i[j]], 1);
            }
        }
    }
}

// ---------------- grouped fp16 GEMM, BM=256, all-cp.async loaders ----------------
__global__ void __launch_bounds__(NTHR, 1) gemm_kernel(
    const __half* __restrict__ A, int lda,
    const __half* __restrict__ Wra, const __half* __restrict__ Wsa,
    const __half* __restrict__ Wrb, const __half* __restrict__ Wsb,
    int Kdim, int ybnd, float* __restrict__ Ca, float* __restrict__ Cb,
    int ldc, int gather)
{
    const int g     = blockIdx.z;
    const int mtile = blockIdx.x;
    const int y     = blockIdx.y;

    int m_count, base_pos;
    if (g < EE) { m_count = g_counts[g]; base_pos = g_offsets[g]; }
    else        { m_count = TT;          base_pos = NROUTED; }
    if (mtile * BM >= m_count) return;
    const int rows = min(BM, m_count - mtile * BM);

    const size_t wsz = (size_t)II * HH;
    const __half* W;
    float* C;
    int n0;
    if (y < ybnd) {
        W = (g < EE) ? (Wra + (size_t)g * wsz) : Wsa;
        C = Ca; n0 = y * BN;
    } else {
        W = (g < EE) ? (Wrb + (size_t)g * wsz) : Wsb;
        C = Cb; n0 = (y - ybnd) * BN;
    }

    extern __shared__ char sm[];
    __shared__ int s_toks[BM];
    const unsigned smb = (unsigned)__cvta_generic_to_shared(sm);

    const int tid = threadIdx.x;
    if (tid < BM) {
        int r = min(tid, rows - 1);
        int pos = base_pos + mtile*BM + r;
        s_toks[tid] = gather ? ((g < EE) ? g_pair_token[pos] : (mtile*BM + r)) : pos;
    }
    __syncthreads();

    const int S = Kdim / BK;
    const int warp = tid >> 5, lane = tid & 31;
    const int wm = (warp & 3) * 64;
    const int wn = (warp >> 2) * 32;
    const int l15 = lane & 15, lh = lane >> 4;

    float acc[4][4][4];
    #pragma unroll
    for (int i = 0; i < 4; ++i)
        #pragma unroll
        for (int j = 0; j < 4; ++j)
            #pragma unroll
            for (int q = 0; q < 4; ++q) acc[i][j][q] = 0.f;

    // ---- stage loader (pure cp.async) ----
    // A: 256 rows x 4 chunks(16B) = 1024 ; B: 128 rows x 4 chunks = 512
    #define LOAD_STAGE(dstb, k0) do {                                        \
        _Pragma("unroll")                                                    \
        for (int t = 0; t < 2; ++t) {                                        \
            int c = tid + t*NTHR;                                            \
            int row = c >> 2, ch = c & 3;                                    \
            const __half* srcp = A + (size_t)s_toks[row]*lda + (k0) + ch*8;  \
            cp16((dstb) + OFF_A + row*ROWB + ch*16, srcp);                   \
        }                                                                    \
        {                                                                    \
            int row = tid >> 2, ch = tid & 3;                                \
            const __half* srcp = W + (size_t)(n0+row)*Kdim + (k0) + ch*8;    \
            cp16((dstb) + OFF_B + row*ROWB + ch*16, srcp);                   \
        }                                                                    \
        asm volatile("cp.async.commit_group;");                              \
    } while(0)

    LOAD_STAGE(smb, 0);
    asm volatile("cp.async.wait_group 0;" ::: "memory");
    __syncthreads();

    int buf = 0;
    for (int s = 0; s < S; ++s) {
        const unsigned cb = smb + buf * BUFSZ;
        const unsigned nb = smb + (buf ^ 1) * BUFSZ;
        if (s + 1 < S) LOAD_STAGE(nb, (s + 1) * BK);

        #pragma unroll
        for (int kk = 0; kk < BK; kk += 16) {
            unsigned bh[2][4];
            #pragma unroll
            for (int nf2 = 0; nf2 < 2; ++nf2) {
                unsigned addr = cb + OFF_B + (wn + nf2*16 + l15)*ROWB + (kk + lh*8)*2;
                ldsm4(bh[nf2][0], bh[nf2][1], bh[nf2][2], bh[nf2][3], addr);
            }
            #pragma unroll
            for (int mf = 0; mf < 4; ++mf) {
                unsigned ah[4];
                unsigned addr = cb + OFF_A + (wm + mf*16 + l15)*ROWB + (kk + lh*8)*2;
                ldsm4(ah[0], ah[1], ah[2], ah[3], addr);
                #pragma unroll
                for (int nf2 = 0; nf2 < 2; ++nf2) {
                    #pragma unroll
                    for (int u = 0; u < 2; ++u) {
                        mma16816(acc[mf][nf2*2 + u], ah, bh[nf2][u], bh[nf2][2 + u]);
                    }
                }
            }
        }

        if (s + 1 < S)
            asm volatile("cp.async.wait_group 0;" ::: "memory");
        __syncthreads();
        buf ^= 1;
    }

    // ---- epilogue ----
    const int gq = lane >> 2, tau = lane & 3;
    #pragma unroll
    for (int mf = 0; mf < 4; ++mf) {
        #pragma unroll
        for (int nf = 0; nf < 4; ++nf) {
            int col = n0 + wn + nf*8 + tau*2;
            int r0 = wm + mf*16 + gq;
            int r1 = r0 + 8;
            if (r0 < rows) {
                float* d = C + (size_t)(base_pos + mtile*BM + r0) * ldc + col;
                d[0] = acc[mf][nf][0]; d[1] = acc[mf][nf][1];
            }
            if (r1 < rows) {
                float* d = C + (size_t)(base_pos + mtile*BM + r1) * ldc + col;
                d[0] = acc[mf][nf][2]; d[1] = acc[mf][nf][3];
            }
        }
    }
}

// ---------------- combine ----------------
__global__ __launch_bounds__(256) void combine_kernel(float* __restrict__ out)
{
    const int t = blockIdx.x;
    const int tid = threadIdx.x;
    __shared__ float w[TOPK];
    __shared__ int   pos[TOPK];
    if (tid < TOPK) {
        w[tid]   = g_topk_w[t*TOPK + tid];
        pos[tid] = g_pair_pos[t*TOPK + tid];
    }
    __syncthreads();
    const float4* sh = (const float4*)(g_pairout + (size_t)(NROUTED + t) * HH);
    const float4* p0 = (const float4*)(g_pairout + (size_t)pos[0] * HH);
    const float4* p1 = (const float4*)(g_pairout + (size_t)pos[1] * HH);
    const float4* p2 = (const float4*)(g_pairout + (size_t)pos[2] * HH);
    const float4* p3 = (const float4*)(g_pairout + (size_t)pos[3] * HH);
    float4* o = (float4*)(out + (size_t)t * HH);
    const float w0=w[0], w1=w[1], w2=w[2], w3=w[3];
    #pragma unroll
    for (int it = 0; it < HH/4/256; ++it) {
        int i = tid + it*256;
        float4 acc = sh[i];
        float4 v0 = p0[i], v1 = p1[i], v2 = p2[i], v3 = p3[i];
        acc.x += w0*v0.x + w1*v1.x + w2*v2.x + w3*v3.x;
        acc.y += w0*v0.y + w1*v1.y + w2*v2.y + w3*v3.y;
        acc.z += w0*v0.z + w1*v1.z + w2*v2.z + w3*v3.z;
        acc.w += w0*v0.w + w1*v1.w + w2*v2.w + w3*v3.w;
        o[i] = acc;
    }
}

// ---------------- launch ----------------
extern "C" void kernel_launch(void* const* d_in, const int* in_sizes, int n_in,
                              void* d_out, int out_size)
{
    const float* x    = (const float*)d_in[0];
    const float* gw   = (const float*)d_in[1];
    const float* bias = (const float*)d_in[2];
    const float* w1   = (const float*)d_in[3];
    const float* w3   = (const float*)d_in[4];
    const float* w2   = (const float*)d_in[5];
    const float* ws1  = (const float*)d_in[6];
    const float* ws3  = (const float*)d_in[7];
    const float* ws2  = (const float*)d_in[8];
    float* out = (float*)d_out;

    cudaFuncSetAttribute(gemm_kernel, cudaFuncAttributeMaxDynamicSharedMemorySize, SMEM_DYN);

    convw_kernel<<<(int)(WTOT/2048), 256>>>(w1, w3, w2, ws1, ws3, ws2);
    gate_kernel<<<TT/4, 256>>>(x, gw, bias);
    offsets_kernel<<<1, 32>>>();
    scatter_kernel<<<TT/256, 256>>>();
    convx_kernel<<<TT*HH/256, 256>>>(x);

    __half *wh, *xh, *ah;
    cudaGetSymbolAddress((void**)&wh, g_wh);
    cudaGetSymbolAddress((void**)&xh, g_xh);
    cudaGetSymbolAddress((void**)&ah, g_acth);
    float *c1, *c3, *po;
    cudaGetSymbolAddress((void**)&c1, g_C1);
    cudaGetSymbolAddress((void**)&c3, g_C3);
    cudaGetSymbolAddress((void**)&po, g_pairout);

    // phase A: C1 = X@W1^T (y<8), C3 = X@W3^T (y>=8); K=HH
    gemm_kernel<<<dim3(8, 16, EE+1), NTHR, SMEM_DYN>>>(
        xh, HH, wh + OW1, wh + OWS1, wh + OW3, wh + OWS3, HH, 8, c1, c3, II, 1);
    act_kernel<<<(int)((size_t)NPAIRS*II/4/256), 256>>>();
    // phase B: pairout = act@W2^T; K=II
    gemm_kernel<<<dim3(8, 16, EE+1), NTHR, SMEM_DYN>>>(
        ah, II, wh + OW2, wh + OWS2, wh + OW2, wh + OWS2, II, 16, po, po, HH, 0);
    combine_kernel<<<TT, 256>>>(out);
}

// round 10
// speedup vs baseline: 2.2731x; 1.2753x over previous
#include <cuda_runtime.h>
#include <cuda_fp16.h>
#include <math.h>
#include <stdint.h>

#define TT 2048
#define HH 2048
#define II 1024
#define EE 32
#define TOPK 4
#define NROUTED (TT*TOPK)
#define NPAIRS  (NROUTED + TT)

// GEMM tiling (R7-proven shape)
#define BM 128
#define BN 128
#define BK 32
#define NTHR 256
#define ROWB 80
#define OFF_A 0
#define OFF_B 10240
#define BUFSZ 20480
#define NSTAGE 3
#define SMEM_DYN (NSTAGE*BUFSZ)

// fp16 weight cache layout (element offsets)
#define OW1  0ULL
#define OW3  67108864ULL
#define OW2  134217728ULL
#define OWS1 201326592ULL
#define OWS3 203423744ULL
#define OWS2 205520896ULL
#define WTOT 207618048ULL

// ---------------- device scratch ----------------
__device__ int   g_counts[EE];
__device__ int   g_cursor[EE];
__device__ int   g_offsets[EE];
__device__ int   g_topk_idx[NROUTED];
__device__ float g_topk_w[NROUTED];
__device__ int   g_pair_token[NROUTED];
__device__ int   g_pair_pos[NROUTED];
__device__ __half g_wh[WTOT];
__device__ __half g_xh[(size_t)TT*HH];
__device__ float g_C1[(size_t)NPAIRS*II];
__device__ float g_C3[(size_t)NPAIRS*II];
__device__ __half g_acth[(size_t)NPAIRS*II];
__device__ float g_pairout[(size_t)NPAIRS*HH];

// ---------------- helpers ----------------
__device__ __forceinline__ void cvt2h(unsigned &r, float hi_elem, float lo_elem) {
    asm("cvt.rn.f16x2.f32 %0, %1, %2;" : "=r"(r) : "f"(hi_elem), "f"(lo_elem));
}
__device__ __forceinline__ void ldsm4(unsigned &r0, unsigned &r1, unsigned &r2, unsigned &r3,
                                      unsigned addr) {
    asm volatile("ldmatrix.sync.aligned.m8n8.x4.shared.b16 {%0,%1,%2,%3}, [%4];"
                 : "=r"(r0), "=r"(r1), "=r"(r2), "=r"(r3) : "r"(addr));
}
__device__ __forceinline__ void mma16816(float* c, const unsigned* a, unsigned b0, unsigned b1) {
    asm volatile("mma.sync.aligned.m16n8k16.row.col.f32.f16.f16.f32 "
                 "{%0,%1,%2,%3}, {%4,%5,%6,%7}, {%8,%9}, {%0,%1,%2,%3};"
                 : "+f"(c[0]), "+f"(c[1]), "+f"(c[2]), "+f"(c[3])
                 : "r"(a[0]), "r"(a[1]), "r"(a[2]), "r"(a[3]), "r"(b0), "r"(b1));
}
__device__ __forceinline__ void cp16(unsigned dst, const void* src) {
    asm volatile("cp.async.cg.shared.global [%0], [%1], 16;" :: "r"(dst), "l"(src));
}

// ---------------- weight conversion (runs first; also zeroes counters) ----------------
__global__ __launch_bounds__(256) void convw_kernel(
        const float* __restrict__ w1, const float* __restrict__ w3,
        const float* __restrict__ w2, const float* __restrict__ ws1,
        const float* __restrict__ ws3, const float* __restrict__ ws2)
{
    if (blockIdx.x == 0 && threadIdx.x < EE) {
        g_counts[threadIdx.x] = 0; g_cursor[threadIdx.x] = 0;
    }
    size_t base = (size_t)blockIdx.x * 2048 + (size_t)threadIdx.x * 8;
    const float* src; size_t off;
    if      (base < OW3)  { src = w1;  off = base - OW1;  }
    else if (base < OW2)  { src = w3;  off = base - OW3;  }
    else if (base < OWS1) { src = w2;  off = base - OW2;  }
    else if (base < OWS3) { src = ws1; off = base - OWS1; }
    else if (base < OWS2) { src = ws3; off = base - OWS3; }
    else                  { src = ws2; off = base - OWS2; }
    float4 a = *(const float4*)(src + off);
    float4 b = *(const float4*)(src + off + 4);
    unsigned h01, h23, h45, h67;
    cvt2h(h01, a.y, a.x); cvt2h(h23, a.w, a.z);
    cvt2h(h45, b.y, b.x); cvt2h(h67, b.w, b.z);
    *(uint4*)(g_wh + base) = make_uint4(h01, h23, h45, h67);
}

// ---------------- small kernels ----------------
__global__ void offsets_kernel() {
    if (threadIdx.x == 0) {
        int s = 0;
        for (int e = 0; e < EE; ++e) { g_offsets[e] = s; s += g_counts[e]; }
    }
}
__global__ void scatter_kernel() {
    int t = blockIdx.x * blockDim.x + threadIdx.x;
    if (t >= TT) return;
    #pragma unroll
    for (int j = 0; j < TOPK; ++j) {
        int e = g_topk_idx[t*TOPK + j];
        int pos = g_offsets[e] + atomicAdd(&g_cursor[e], 1);
        g_pair_token[pos] = t;
        g_pair_pos[t*TOPK + j] = pos;
    }
}
__global__ __launch_bounds__(256) void convx_kernel(const float* __restrict__ x) {
    int i = blockIdx.x * 256 + threadIdx.x;
    g_xh[i] = __float2half_rn(x[i]);
}
__global__ __launch_bounds__(256) void act_kernel() {
    size_t i4 = (size_t)blockIdx.x * 256 + threadIdx.x;
    float4 a = ((const float4*)g_C1)[i4];
    float4 b = ((const float4*)g_C3)[i4];
    float v0 = a.x / (1.f + expf(-a.x)) * b.x;
    float v1 = a.y / (1.f + expf(-a.y)) * b.y;
    float v2 = a.z / (1.f + expf(-a.z)) * b.z;
    float v3 = a.w / (1.f + expf(-a.w)) * b.w;
    unsigned h01, h23;
    cvt2h(h01, v1, v0);
    cvt2h(h23, v3, v2);
    ((uint2*)g_acth)[i4] = make_uint2(h01, h23);
}

// ---------------- gate + routing (proven) ----------------
__global__ __launch_bounds__(256) void gate_kernel(
        const float* __restrict__ x, const float* __restrict__ gw,
        const float* __restrict__ bias)
{
    __shared__ float xs[4][HH];
    __shared__ float logits_s[4][EE];
    __shared__ float bias_s[EE];
    int tid = threadIdx.x;
    int t0  = blockIdx.x * 4;
    const float4* xg  = (const float4*)(x + (size_t)t0 * HH);
    float4*       xs4 = (float4*)&xs[0][0];
    #pragma unroll
    for (int i = 0; i < 8; ++i) xs4[tid + i*256] = xg[tid + i*256];
    if (tid < EE) bias_s[tid] = bias[tid];
    __syncthreads();
    int warp = tid >> 5, lane = tid & 31;
    #pragma unroll
    for (int ei = 0; ei < 4; ++ei) {
        int e = warp*4 + ei;
        const float* gr = gw + (size_t)e * HH;
        float a0=0.f, a1=0.f, a2=0.f, a3=0.f;
        for (int h = lane; h < HH; h += 32) {
            float g = gr[h];
            a0 = fmaf(g, xs[0][h], a0); a1 = fmaf(g, xs[1][h], a1);
            a2 = fmaf(g, xs[2][h], a2); a3 = fmaf(g, xs[3][h], a3);
        }
        #pragma unroll
        for (int off = 16; off; off >>= 1) {
            a0 += __shfl_xor_sync(0xffffffffu, a0, off);
            a1 += __shfl_xor_sync(0xffffffffu, a1, off);
            a2 += __shfl_xor_sync(0xffffffffu, a2, off);
            a3 += __shfl_xor_sync(0xffffffffu, a3, off);
        }
        if (lane == 0) {
            logits_s[0][e] = a0; logits_s[1][e] = a1;
            logits_s[2][e] = a2; logits_s[3][e] = a3;
        }
    }
    __syncthreads();
    if (warp < 4) {
        int t = t0 + warp;
        float logit = logits_s[warp][lane];
        float s   = 1.f / (1.f + expf(-logit));
        float sfc = s + bias_s[lane];
        float m1 = sfc, m2 = -INFINITY;
        #pragma unroll
        for (int off = 4; off >= 1; off >>= 1) {
            float o1 = __shfl_xor_sync(0xffffffffu, m1, off);
            float o2 = __shfl_xor_sync(0xffffffffu, m2, off);
            float hi = fmaxf(m1, o1);
            float lo = fmaxf(fminf(m1, o1), fmaxf(m2, o2));
            m1 = hi; m2 = lo;
        }
        float gs = m1 + m2;
        float gv[4];
        gv[0] = __shfl_sync(0xffffffffu, gs, 0);
        gv[1] = __shfl_sync(0xffffffffu, gs, 8);
        gv[2] = __shfl_sync(0xffffffffu, gs, 16);
        gv[3] = __shfl_sync(0xffffffffu, gs, 24);
        int b1 = 0; float v1 = gv[0];
        #pragma unroll
        for (int gg = 1; gg < 4; ++gg) if (gv[gg] > v1) { v1 = gv[gg]; b1 = gg; }
        int b2 = -1; float v2 = -INFINITY;
        #pragma unroll
        for (int gg = 0; gg < 4; ++gg) {
            if (gg == b1) continue;
            if (gv[gg] > v2) { v2 = gv[gg]; b2 = gg; }
        }
        int mygrp = lane >> 3;
        float val = (mygrp == b1 || mygrp == b2) ? sfc : 0.0f;
        int sel_i[TOPK]; float sel_w[TOPK];
        float cur = val;
        #pragma unroll
        for (int j = 0; j < TOPK; ++j) {
            float bv = cur; int bi = lane;
            #pragma unroll
            for (int off = 16; off >= 1; off >>= 1) {
                float ov = __shfl_xor_sync(0xffffffffu, bv, off);
                int   oi = __shfl_xor_sync(0xffffffffu, bi, off);
                if (ov > bv || (ov == bv && oi < bi)) { bv = ov; bi = oi; }
            }
            sel_i[j] = bi;
            sel_w[j] = __shfl_sync(0xffffffffu, s, bi);
            if (lane == bi) cur = -INFINITY;
        }
        if (lane == 0) {
            float sum = sel_w[0] + sel_w[1] + sel_w[2] + sel_w[3];
            float scale = 2.5f / (sum + 1e-20f);
            #pragma unroll
            for (int j = 0; j < TOPK; ++j) {
                g_topk_idx[t*TOPK + j] = sel_i[j];
                g_topk_w[t*TOPK + j]   = sel_w[j] * scale;
                atomicAdd(&g_counts[sel_i[j]], 1);
            }
        }
    }
}

// ---------------- grouped fp16 GEMM: BM=128, 3-stage cp.async pipeline ----------------
__global__ void __launch_bounds__(NTHR, 2) gemm_kernel(
    const __half* __restrict__ A, int lda,
    const __half* __restrict__ Wra, const __half* __restrict__ Wsa,
    const __half* __restrict__ Wrb, const __half* __restrict__ Wsb,
    int Kdim, int ybnd, float* __restrict__ Ca, float* __restrict__ Cb,
    int ldc, int gather)
{
    const int g     = blockIdx.z;
    const int mtile = blockIdx.x;
    const int y     = blockIdx.y;

    int m_count, base_pos;
    if (g < EE) { m_count = g_counts[g]; base_pos = g_offsets[g]; }
    else        { m_count = TT;          base_pos = NROUTED; }
    if (mtile * BM >= m_count) return;
    const int rows = min(BM, m_count - mtile * BM);

    const size_t wsz = (size_t)II * HH;
    const __half* W;
    float* C;
    int n0;
    if (y < ybnd) {
        W = (g < EE) ? (Wra + (size_t)g * wsz) : Wsa;
        C = Ca; n0 = y * BN;
    } else {
        W = (g < EE) ? (Wrb + (size_t)g * wsz) : Wsb;
        C = Cb; n0 = (y - ybnd) * BN;
    }

    extern __shared__ char sm[];
    __shared__ int s_toks[BM];
    const unsigned smb = (unsigned)__cvta_generic_to_shared(sm);

    const int tid = threadIdx.x;
    if (tid < BM) {
        int r = min(tid, rows - 1);
        int pos = base_pos + mtile*BM + r;
        s_toks[tid] = gather ? ((g < EE) ? g_pair_token[pos] : (mtile*BM + r)) : pos;
    }
    __syncthreads();

    const int S = Kdim / BK;
    const int warp = tid >> 5, lane = tid & 31;
    const int wm = (warp & 1) * 64;
    const int wn = (warp >> 1) * 32;
    const int l15 = lane & 15, lh = lane >> 4;

    float acc[4][4][4];
    #pragma unroll
    for (int i = 0; i < 4; ++i)
        #pragma unroll
        for (int j = 0; j < 4; ++j)
            #pragma unroll
            for (int q = 0; q < 4; ++q) acc[i][j][q] = 0.f;

    // A: 128 rows x 4 chunks = 512 -> 2/thread ; B: same
    #define LOAD_STAGE(dstb, k0) do {                                        \
        _Pragma("unroll")                                                    \
        for (int t = 0; t < 2; ++t) {                                        \
            int c = tid + t*NTHR;                                            \
            int row = c >> 2, ch = c & 3;                                    \
            const __half* srcp = A + (size_t)s_toks[row]*lda + (k0) + ch*8;  \
            cp16((dstb) + OFF_A + row*ROWB + ch*16, srcp);                   \
        }                                                                    \
        _Pragma("unroll")                                                    \
        for (int t = 0; t < 2; ++t) {                                        \
            int c = tid + t*NTHR;                                            \
            int row = c >> 2, ch = c & 3;                                    \
            const __half* srcp = W + (size_t)(n0+row)*Kdim + (k0) + ch*8;    \
            cp16((dstb) + OFF_B + row*ROWB + ch*16, srcp);                   \
        }                                                                    \
        asm volatile("cp.async.commit_group;");                              \
    } while(0)

    LOAD_STAGE(smb, 0);
    if (S > 1) LOAD_STAGE(smb + BUFSZ, BK);

    for (int s = 0; s < S; ++s) {
        asm volatile("cp.async.wait_group 1;" ::: "memory");
        __syncthreads();
        const unsigned cb = smb + (s % NSTAGE) * BUFSZ;
        if (s + 2 < S) {
            const unsigned nb = smb + ((s + 2) % NSTAGE) * BUFSZ;
            LOAD_STAGE(nb, (s + 2) * BK);
        } else {
            asm volatile("cp.async.commit_group;");   // keep group count in sync
        }

        #pragma unroll
        for (int kk = 0; kk < BK; kk += 16) {
            unsigned bh[2][4];
            #pragma unroll
            for (int nf2 = 0; nf2 < 2; ++nf2) {
                unsigned addr = cb + OFF_B + (wn + nf2*16 + l15)*ROWB + (kk + lh*8)*2;
                ldsm4(bh[nf2][0], bh[nf2][1], bh[nf2][2], bh[nf2][3], addr);
            }
            #pragma unroll
            for (int mf = 0; mf < 4; ++mf) {
                unsigned ah[4];
                unsigned addr = cb + OFF_A + (wm + mf*16 + l15)*ROWB + (kk + lh*8)*2;
                ldsm4(ah[0], ah[1], ah[2], ah[3], addr);
                #pragma unroll
                for (int nf2 = 0; nf2 < 2; ++nf2) {
                    #pragma unroll
                    for (int u = 0; u < 2; ++u) {
                        mma16816(acc[mf][nf2*2 + u], ah, bh[nf2][u], bh[nf2][2 + u]);
                    }
                }
            }
        }
        __syncthreads();
    }

    // ---- epilogue ----
    const int gq = lane >> 2, tau = lane & 3;
    #pragma unroll
    for (int mf = 0; mf < 4; ++mf) {
        #pragma unroll
        for (int nf = 0; nf < 4; ++nf) {
            int col = n0 + wn + nf*8 + tau*2;
            int r0 = wm + mf*16 + gq;
            int r1 = r0 + 8;
            if (r0 < rows) {
                float* d = C + (size_t)(base_pos + mtile*BM + r0) * ldc + col;
                d[0] = acc[mf][nf][0]; d[1] = acc[mf][nf][1];
            }
            if (r1 < rows) {
                float* d = C + (size_t)(base_pos + mtile*BM + r1) * ldc + col;
                d[0] = acc[mf][nf][2]; d[1] = acc[mf][nf][3];
            }
        }
    }
}

// ---------------- combine ----------------
__global__ __launch_bounds__(256) void combine_kernel(float* __restrict__ out)
{
    const int t = blockIdx.x;
    const int tid = threadIdx.x;
    __shared__ float w[TOPK];
    __shared__ int   pos[TOPK];
    if (tid < TOPK) {
        w[tid]   = g_topk_w[t*TOPK + tid];
        pos[tid] = g_pair_pos[t*TOPK + tid];
    }
    __syncthreads();
    const float4* sh = (const float4*)(g_pairout + (size_t)(NROUTED + t) * HH);
    const float4* p0 = (const float4*)(g_pairout + (size_t)pos[0] * HH);
    const float4* p1 = (const float4*)(g_pairout + (size_t)pos[1] * HH);
    const float4* p2 = (const float4*)(g_pairout + (size_t)pos[2] * HH);
    const float4* p3 = (const float4*)(g_pairout + (size_t)pos[3] * HH);
    float4* o = (float4*)(out + (size_t)t * HH);
    const float w0=w[0], w1=w[1], w2=w[2], w3=w[3];
    #pragma unroll
    for (int it = 0; it < HH/4/256; ++it) {
        int i = tid + it*256;
        float4 acc = sh[i];
        float4 v0 = p0[i], v1 = p1[i], v2 = p2[i], v3 = p3[i];
        acc.x += w0*v0.x + w1*v1.x + w2*v2.x + w3*v3.x;
        acc.y += w0*v0.y + w1*v1.y + w2*v2.y + w3*v3.y;
        acc.z += w0*v0.z + w1*v1.z + w2*v2.z + w3*v3.z;
        acc.w += w0*v0.w + w1*v1.w + w2*v2.w + w3*v3.w;
        o[i] = acc;
    }
}

// ---------------- launch ----------------
extern "C" void kernel_launch(void* const* d_in, const int* in_sizes, int n_in,
                              void* d_out, int out_size)
{
    const float* x    = (const float*)d_in[0];
    const float* gw   = (const float*)d_in[1];
    const float* bias = (const float*)d_in[2];
    const float* w1   = (const float*)d_in[3];
    const float* w3   = (const float*)d_in[4];
    const float* w2   = (const float*)d_in[5];
    const float* ws1  = (const float*)d_in[6];
    const float* ws3  = (const float*)d_in[7];
    const float* ws2  = (const float*)d_in[8];
    float* out = (float*)d_out;

    cudaFuncSetAttribute(gemm_kernel, cudaFuncAttributeMaxDynamicSharedMemorySize, SMEM_DYN);

    convw_kernel<<<(int)(WTOT/2048), 256>>>(w1, w3, w2, ws1, ws3, ws2);
    gate_kernel<<<TT/4, 256>>>(x, gw, bias);
    offsets_kernel<<<1, 32>>>();
    scatter_kernel<<<TT/256, 256>>>();
    convx_kernel<<<TT*HH/256, 256>>>(x);

    __half *wh, *xh, *ah;
    cudaGetSymbolAddress((void**)&wh, g_wh);
    cudaGetSymbolAddress((void**)&xh, g_xh);
    cudaGetSymbolAddress((void**)&ah, g_acth);
    float *c1, *c3, *po;
    cudaGetSymbolAddress((void**)&c1, g_C1);
    cudaGetSymbolAddress((void**)&c3, g_C3);
    cudaGetSymbolAddress((void**)&po, g_pairout);

    // phase A: C1 = X@W1^T (y<8), C3 = X@W3^T (y>=8); K=HH
    gemm_kernel<<<dim3(16, 16, EE+1), NTHR, SMEM_DYN>>>(
        xh, HH, wh + OW1, wh + OWS1, wh + OW3, wh + OWS3, HH, 8, c1, c3, II, 1);
    act_kernel<<<(int)((size_t)NPAIRS*II/4/256), 256>>>();
    // phase B: pairout = act@W2^T; K=II
    gemm_kernel<<<dim3(16, 16, EE+1), NTHR, SMEM_DYN>>>(
        ah, II, wh + OW2, wh + OWS2, wh + OW2, wh + OWS2, II, 16, po, po, HH, 0);
    combine_kernel<<<TT, 256>>>(out);
}

// round 11
// speedup vs baseline: 2.8640x; 1.2599x over previous
#include <cuda_runtime.h>
#include <cuda_fp16.h>
#include <math.h>
#include <stdint.h>

#define TT 2048
#define HH 2048
#define II 1024
#define EE 32
#define TOPK 4
#define NROUTED (TT*TOPK)
#define NPAIRS  (NROUTED + TT)

// GEMM tiling: BM=128, BN=128, BK=64, 256 thr, 2 CTA/SM
#define BM 128
#define BN 128
#define BK 64
#define NTHR 256
#define ROWB 144                   // 64 fp16 = 128B + 16B pad
#define OFF_A 0
#define OFF_B 18432                // 128*144
#define BUFSZ 36864
#define SMEM_DYN (2*BUFSZ)

// ---------------- device scratch ----------------
__device__ int   g_counts[EE];
__device__ int   g_cursor[EE];
__device__ int   g_offsets[EE];
__device__ int   g_topk_idx[NROUTED];
__device__ float g_topk_w[NROUTED];
__device__ int   g_pair_token[NROUTED];
__device__ int   g_pair_pos[NROUTED];
__device__ __half g_xh[(size_t)TT*HH];
__device__ float g_C1[(size_t)NPAIRS*II];
__device__ float g_C3[(size_t)NPAIRS*II];
__device__ __half g_acth[(size_t)NPAIRS*II];
__device__ float g_pairout[(size_t)NPAIRS*HH];

// ---------------- helpers ----------------
__device__ __forceinline__ void cvt2h(unsigned &r, float hi_elem, float lo_elem) {
    asm("cvt.rn.f16x2.f32 %0, %1, %2;" : "=r"(r) : "f"(hi_elem), "f"(lo_elem));
}
__device__ __forceinline__ void ldsm4(unsigned &r0, unsigned &r1, unsigned &r2, unsigned &r3,
                                      unsigned addr) {
    asm volatile("ldmatrix.sync.aligned.m8n8.x4.shared.b16 {%0,%1,%2,%3}, [%4];"
                 : "=r"(r0), "=r"(r1), "=r"(r2), "=r"(r3) : "r"(addr));
}
__device__ __forceinline__ void mma16816(float* c, const unsigned* a, unsigned b0, unsigned b1) {
    asm volatile("mma.sync.aligned.m16n8k16.row.col.f32.f16.f16.f32 "
                 "{%0,%1,%2,%3}, {%4,%5,%6,%7}, {%8,%9}, {%0,%1,%2,%3};"
                 : "+f"(c[0]), "+f"(c[1]), "+f"(c[2]), "+f"(c[3])
                 : "r"(a[0]), "r"(a[1]), "r"(a[2]), "r"(a[3]), "r"(b0), "r"(b1));
}
__device__ __forceinline__ void cp16(unsigned dst, const void* src) {
    asm volatile("cp.async.cg.shared.global [%0], [%1], 16;" :: "r"(dst), "l"(src));
}

// ---------------- small kernels ----------------
__global__ void zero_kernel() {
    int i = threadIdx.x;
    if (i < EE) { g_counts[i] = 0; g_cursor[i] = 0; }
}
__global__ void offsets_kernel() {
    if (threadIdx.x == 0) {
        int s = 0;
        for (int e = 0; e < EE; ++e) { g_offsets[e] = s; s += g_counts[e]; }
    }
}
__global__ void scatter_kernel() {
    int t = blockIdx.x * blockDim.x + threadIdx.x;
    if (t >= TT) return;
    #pragma unroll
    for (int j = 0; j < TOPK; ++j) {
        int e = g_topk_idx[t*TOPK + j];
        int pos = g_offsets[e] + atomicAdd(&g_cursor[e], 1);
        g_pair_token[pos] = t;
        g_pair_pos[t*TOPK + j] = pos;
    }
}
__global__ __launch_bounds__(256) void convx_kernel(const float* __restrict__ x) {
    int i = blockIdx.x * 256 + threadIdx.x;
    g_xh[i] = __float2half_rn(x[i]);
}
__global__ __launch_bounds__(256) void act_kernel() {
    size_t i4 = (size_t)blockIdx.x * 256 + threadIdx.x;
    float4 a = ((const float4*)g_C1)[i4];
    float4 b = ((const float4*)g_C3)[i4];
    float v0 = a.x / (1.f + expf(-a.x)) * b.x;
    float v1 = a.y / (1.f + expf(-a.y)) * b.y;
    float v2 = a.z / (1.f + expf(-a.z)) * b.z;
    float v3 = a.w / (1.f + expf(-a.w)) * b.w;
    unsigned h01, h23;
    cvt2h(h01, v1, v0);
    cvt2h(h23, v3, v2);
    ((uint2*)g_acth)[i4] = make_uint2(h01, h23);
}

// ---------------- gate + routing (proven) ----------------
__global__ __launch_bounds__(256) void gate_kernel(
        const float* __restrict__ x, const float* __restrict__ gw,
        const float* __restrict__ bias)
{
    __shared__ float xs[4][HH];
    __shared__ float logits_s[4][EE];
    __shared__ float bias_s[EE];
    int tid = threadIdx.x;
    int t0  = blockIdx.x * 4;
    const float4* xg  = (const float4*)(x + (size_t)t0 * HH);
    float4*       xs4 = (float4*)&xs[0][0];
    #pragma unroll
    for (int i = 0; i < 8; ++i) xs4[tid + i*256] = xg[tid + i*256];
    if (tid < EE) bias_s[tid] = bias[tid];
    __syncthreads();
    int warp = tid >> 5, lane = tid & 31;
    #pragma unroll
    for (int ei = 0; ei < 4; ++ei) {
        int e = warp*4 + ei;
        const float* gr = gw + (size_t)e * HH;
        float a0=0.f, a1=0.f, a2=0.f, a3=0.f;
        for (int h = lane; h < HH; h += 32) {
            float g = gr[h];
            a0 = fmaf(g, xs[0][h], a0); a1 = fmaf(g, xs[1][h], a1);
            a2 = fmaf(g, xs[2][h], a2); a3 = fmaf(g, xs[3][h], a3);
        }
        #pragma unroll
        for (int off = 16; off; off >>= 1) {
            a0 += __shfl_xor_sync(0xffffffffu, a0, off);
            a1 += __shfl_xor_sync(0xffffffffu, a1, off);
            a2 += __shfl_xor_sync(0xffffffffu, a2, off);
            a3 += __shfl_xor_sync(0xffffffffu, a3, off);
        }
        if (lane == 0) {
            logits_s[0][e] = a0; logits_s[1][e] = a1;
            logits_s[2][e] = a2; logits_s[3][e] = a3;
        }
    }
    __syncthreads();
    if (warp < 4) {
        int t = t0 + warp;
        float logit = logits_s[warp][lane];
        float s   = 1.f / (1.f + expf(-logit));
        float sfc = s + bias_s[lane];
        float m1 = sfc, m2 = -INFINITY;
        #pragma unroll
        for (int off = 4; off >= 1; off >>= 1) {
            float o1 = __shfl_xor_sync(0xffffffffu, m1, off);
            float o2 = __shfl_xor_sync(0xffffffffu, m2, off);
            float hi = fmaxf(m1, o1);
            float lo = fmaxf(fminf(m1, o1), fmaxf(m2, o2));
            m1 = hi; m2 = lo;
        }
        float gs = m1 + m2;
        float gv[4];
        gv[0] = __shfl_sync(0xffffffffu, gs, 0);
        gv[1] = __shfl_sync(0xffffffffu, gs, 8);
        gv[2] = __shfl_sync(0xffffffffu, gs, 16);
        gv[3] = __shfl_sync(0xffffffffu, gs, 24);
        int b1 = 0; float v1 = gv[0];
        #pragma unroll
        for (int gg = 1; gg < 4; ++gg) if (gv[gg] > v1) { v1 = gv[gg]; b1 = gg; }
        int b2 = -1; float v2 = -INFINITY;
        #pragma unroll
        for (int gg = 0; gg < 4; ++gg) {
            if (gg == b1) continue;
            if (gv[gg] > v2) { v2 = gv[gg]; b2 = gg; }
        }
        int mygrp = lane >> 3;
        float val = (mygrp == b1 || mygrp == b2) ? sfc : 0.0f;
        int sel_i[TOPK]; float sel_w[TOPK];
        float cur = val;
        #pragma unroll
        for (int j = 0; j < TOPK; ++j) {
            float bv = cur; int bi = lane;
            #pragma unroll
            for (int off = 16; off >= 1; off >>= 1) {
                float ov = __shfl_xor_sync(0xffffffffu, bv, off);
                int   oi = __shfl_xor_sync(0xffffffffu, bi, off);
                if (ov > bv || (ov == bv && oi < bi)) { bv = ov; bi = oi; }
            }
            sel_i[j] = bi;
            sel_w[j] = __shfl_sync(0xffffffffu, s, bi);
            if (lane == bi) cur = -INFINITY;
        }
        if (lane == 0) {
            float sum = sel_w[0] + sel_w[1] + sel_w[2] + sel_w[3];
            float scale = 2.5f / (sum + 1e-20f);
            #pragma unroll
            for (int j = 0; j < TOPK; ++j) {
                g_topk_idx[t*TOPK + j] = sel_i[j];
                g_topk_w[t*TOPK + j]   = sel_w[j] * scale;
                atomicAdd(&g_counts[sel_i[j]], 1);
            }
        }
    }
}

// ---------------- grouped fp16 GEMM: BK=64, half-batched B convert ----------------
__global__ void __launch_bounds__(NTHR, 2) gemm_kernel(
    const __half* __restrict__ A, int lda,
    const float* __restrict__ Wra, const float* __restrict__ Wsa,
    const float* __restrict__ Wrb, const float* __restrict__ Wsb,
    int Kdim, int ybnd, float* __restrict__ Ca, float* __restrict__ Cb,
    int ldc, int gather)
{
    const int g     = blockIdx.z;
    const int mtile = blockIdx.x;
    const int y     = blockIdx.y;

    int m_count, base_pos;
    if (g < EE) { m_count = g_counts[g]; base_pos = g_offsets[g]; }
    else        { m_count = TT;          base_pos = NROUTED; }
    if (mtile * BM >= m_count) return;
    const int rows = min(BM, m_count - mtile * BM);

    const size_t wsz = (size_t)II * HH;
    const float* W;
    float* C;
    int n0;
    if (y < ybnd) {
        W = (g < EE) ? (Wra + (size_t)g * wsz) : Wsa;
        C = Ca; n0 = y * BN;
    } else {
        W = (g < EE) ? (Wrb + (size_t)g * wsz) : Wsb;
        C = Cb; n0 = (y - ybnd) * BN;
    }

    extern __shared__ char sm[];
    __shared__ int s_toks[BM];
    const unsigned smb = (unsigned)__cvta_generic_to_shared(sm);

    const int tid = threadIdx.x;
    if (tid < BM) {
        int r = min(tid, rows - 1);
        int pos = base_pos + mtile*BM + r;
        s_toks[tid] = gather ? ((g < EE) ? g_pair_token[pos] : (mtile*BM + r)) : pos;
    }
    __syncthreads();

    const int S = Kdim / BK;
    const int warp = tid >> 5, lane = tid & 31;
    const int wm = (warp & 1) * 64;
    const int wn = (warp >> 1) * 32;
    const int l15 = lane & 15, lh = lane >> 4;

    // per-thread loader coords
    const int arow = tid >> 1;                 // A: 128 rows x 8 ch -> 4/thread via t
    const int brow = tid >> 1;                 // B half: 128 rows x 4 f4 -> 4/thread

    float acc[4][4][4];
    #pragma unroll
    for (int i = 0; i < 4; ++i)
        #pragma unroll
        for (int j = 0; j < 4; ++j)
            #pragma unroll
            for (int q = 0; q < 4; ++q) acc[i][j][q] = 0.f;

    // A loader: 1024 cp16, 4/thread: c = tid + t*256, row=c>>3, ch=c&7
    #define LOAD_A(dstb, k0) do {                                            \
        _Pragma("unroll")                                                    \
        for (int t = 0; t < 4; ++t) {                                        \
            int c = tid + t*NTHR;                                            \
            int row = c >> 3, ch = c & 7;                                    \
            const __half* srcp = A + (size_t)s_toks[row]*lda + (k0) + ch*8;  \
            cp16((dstb) + OFF_A + row*ROWB + ch*16, srcp);                   \
        }                                                                    \
    } while(0)

    // B half-loader: half h covers fp32 cols [h*32, h*32+32)
    #define LDG_B(bv, k0, h) do {                                            \
        _Pragma("unroll")                                                    \
        for (int t = 0; t < 4; ++t) {                                        \
            int c = tid + t*NTHR;                                            \
            int row = c >> 3, f4 = c & 7;                                    \
            (bv)[t] = *(const float4*)(W + (size_t)(n0+row)*Kdim + (k0) + (h)*32 + f4*4); \
        }                                                                    \
    } while(0)
    #define STS_B(bv, dstg, h) do {                                          \
        _Pragma("unroll")                                                    \
        for (int t = 0; t < 4; ++t) {                                        \
            int c = tid + t*NTHR;                                            \
            int row = c >> 3, f4 = c & 7;                                    \
            unsigned h01, h23;                                               \
            cvt2h(h01, (bv)[t].y, (bv)[t].x);                                \
            cvt2h(h23, (bv)[t].w, (bv)[t].z);                                \
            *(uint2*)((dstg) + OFF_B + row*ROWB + (h)*64 + f4*8) = make_uint2(h01, h23); \
        }                                                                    \
    } while(0)

    // compute half: kk0 = 0 or 32
    #define COMPUTE_HALF(cb, kk0) do {                                       \
        _Pragma("unroll")                                                    \
        for (int kk = (kk0); kk < (kk0) + 32; kk += 16) {                    \
            unsigned bh[2][4];                                               \
            _Pragma("unroll")                                                \
            for (int nf2 = 0; nf2 < 2; ++nf2) {                              \
                unsigned addr = (cb) + OFF_B + (wn + nf2*16 + l15)*ROWB + (kk + lh*8)*2; \
                ldsm4(bh[nf2][0], bh[nf2][1], bh[nf2][2], bh[nf2][3], addr); \
            }                                                                \
            _Pragma("unroll")                                                \
            for (int mf = 0; mf < 4; ++mf) {                                 \
                unsigned ah[4];                                              \
                unsigned addr = (cb) + OFF_A + (wm + mf*16 + l15)*ROWB + (kk + lh*8)*2; \
                ldsm4(ah[0], ah[1], ah[2], ah[3], addr);                     \
                _Pragma("unroll")                                            \
                for (int nf2 = 0; nf2 < 2; ++nf2) {                          \
                    _Pragma("unroll")                                        \
                    for (int u = 0; u < 2; ++u)                              \
                        mma16816(acc[mf][nf2*2 + u], ah, bh[nf2][u], bh[nf2][2 + u]); \
                }                                                            \
            }                                                                \
        }                                                                    \
    } while(0)

    // ---- prologue: fill buffer 0 ----
    {
        float4 bv[4];
        LOAD_A(smb, 0);
        asm volatile("cp.async.commit_group;");
        LDG_B(bv, 0, 0);
        STS_B(bv, sm, 0);
        LDG_B(bv, 0, 1);
        STS_B(bv, sm, 1);
        asm volatile("cp.async.wait_group 0;" ::: "memory");
        __syncthreads();
    }

    int buf = 0;
    for (int s = 0; s < S; ++s) {
        const unsigned cb = smb + buf * BUFSZ;
        const unsigned nb = smb + (buf ^ 1) * BUFSZ;
        char* nbg = sm + (buf ^ 1) * BUFSZ;
        const int k0n = (s + 1) * BK;
        const bool more = (s + 1 < S);
        float4 bv[4];

        if (more) {
            LDG_B(bv, k0n, 0);          // issue half0 LDGs (latency hidden by compute)
            LOAD_A(nb, k0n);            // A cp.async for next stage
            asm volatile("cp.async.commit_group;");
        }
        COMPUTE_HALF(cb, 0);
        if (more) {
            STS_B(bv, nbg, 0);
            LDG_B(bv, k0n, 1);          // half1 LDGs hidden by second compute half
        }
        COMPUTE_HALF(cb, 32);
        if (more) {
            STS_B(bv, nbg, 1);
            asm volatile("cp.async.wait_group 0;" ::: "memory");
        }
        __syncthreads();
        buf ^= 1;
    }

    // ---- epilogue ----
    const int gq = lane >> 2, tau = lane & 3;
    #pragma unroll
    for (int mf = 0; mf < 4; ++mf) {
        #pragma unroll
        for (int nf = 0; nf < 4; ++nf) {
            int col = n0 + wn + nf*8 + tau*2;
            int r0 = wm + mf*16 + gq;
            int r1 = r0 + 8;
            if (r0 < rows) {
                float* d = C + (size_t)(base_pos + mtile*BM + r0) * ldc + col;
                d[0] = acc[mf][nf][0]; d[1] = acc[mf][nf][1];
            }
            if (r1 < rows) {
                float* d = C + (size_t)(base_pos + mtile*BM + r1) * ldc + col;
                d[0] = acc[mf][nf][2]; d[1] = acc[mf][nf][3];
            }
        }
    }
}

// ---------------- combine ----------------
__global__ __launch_bounds__(256) void combine_kernel(float* __restrict__ out)
{
    const int t = blockIdx.x;
    const int tid = threadIdx.x;
    __shared__ float w[TOPK];
    __shared__ int   pos[TOPK];
    if (tid < TOPK) {
        w[tid]   = g_topk_w[t*TOPK + tid];
        pos[tid] = g_pair_pos[t*TOPK + tid];
    }
    __syncthreads();
    const float4* sh = (const float4*)(g_pairout + (size_t)(NROUTED + t) * HH);
    const float4* p0 = (const float4*)(g_pairout + (size_t)pos[0] * HH);
    const float4* p1 = (const float4*)(g_pairout + (size_t)pos[1] * HH);
    const float4* p2 = (const float4*)(g_pairout + (size_t)pos[2] * HH);
    const float4* p3 = (const float4*)(g_pairout + (size_t)pos[3] * HH);
    float4* o = (float4*)(out + (size_t)t * HH);
    const float w0=w[0], w1=w[1], w2=w[2], w3=w[3];
    #pragma unroll
    for (int it = 0; it < HH/4/256; ++it) {
        int i = tid + it*256;
        float4 acc = sh[i];
        float4 v0 = p0[i], v1 = p1[i], v2 = p2[i], v3 = p3[i];
        acc.x += w0*v0.x + w1*v1.x + w2*v2.x + w3*v3.x;
        acc.y += w0*v0.y + w1*v1.y + w2*v2.y + w3*v3.y;
        acc.z += w0*v0.z + w1*v1.z + w2*v2.z + w3*v3.z;
        acc.w += w0*v0.w + w1*v1.w + w2*v2.w + w3*v3.w;
        o[i] = acc;
    }
}

// ---------------- launch ----------------
extern "C" void kernel_launch(void* const* d_in, const int* in_sizes, int n_in,
                              void* d_out, int out_size)
{
    const float* x    = (const float*)d_in[0];
    const float* gw   = (const float*)d_in[1];
    const float* bias = (const float*)d_in[2];
    const float* w1   = (const float*)d_in[3];
    const float* w3   = (const float*)d_in[4];
    const float* w2   = (const float*)d_in[5];
    const float* ws1  = (const float*)d_in[6];
    const float* ws3  = (const float*)d_in[7];
    const float* ws2  = (const float*)d_in[8];
    float* out = (float*)d_out;

    cudaFuncSetAttribute(gemm_kernel, cudaFuncAttributeMaxDynamicSharedMemorySize, SMEM_DYN);

    zero_kernel<<<1, 64>>>();
    gate_kernel<<<TT/4, 256>>>(x, gw, bias);
    offsets_kernel<<<1, 32>>>();
    scatter_kernel<<<TT/256, 256>>>();
    convx_kernel<<<TT*HH/256, 256>>>(x);

    __half *xh, *ah;
    cudaGetSymbolAddress((void**)&xh, g_xh);
    cudaGetSymbolAddress((void**)&ah, g_acth);
    float *c1, *c3, *po;
    cudaGetSymbolAddress((void**)&c1, g_C1);
    cudaGetSymbolAddress((void**)&c3, g_C3);
    cudaGetSymbolAddress((void**)&po, g_pairout);

    // phase A: C1 = X@W1^T (y<8), C3 = X@W3^T (y>=8); K=HH
    gemm_kernel<<<dim3(16, 16, EE+1), NTHR, SMEM_DYN>>>(
        xh, HH, w1, ws1, w3, ws3, HH, 8, c1, c3, II, 1);
    act_kernel<<<(int)((size_t)NPAIRS*II/4/256), 256>>>();
    // phase B: pairout = act@W2^T; K=II
    gemm_kernel<<<dim3(16, 16, EE+1), NTHR, SMEM_DYN>>>(
        ah, II, w2, ws2, w2, ws2, II, 16, po, po, HH, 0);
    combine_kernel<<<TT, 256>>>(out);
}